// round 3
// baseline (speedup 1.0000x reference)
#include <cuda_runtime.h>
#include <cuda_bf16.h>

#define NB 64
#define NT 512
#define ND 1024
#define BPB 8  // batches per block in kernel B

// scratch: packed (chain_pos | role<<16) per (b,t). Static device global.
__device__ int g_packed[NB * NT];

// ---------------------------------------------------------------------------
// Kernel A: per-batch-row prefix scans (cumsum + cummax) via warp shuffles.
// ---------------------------------------------------------------------------
__global__ __launch_bounds__(512) void gpe_scan_kernel(
    const int* __restrict__ input_ids,
    const int* __restrict__ rel_ids) {
    __shared__ int wred[16];

    const int b = blockIdx.x;
    const int t = threadIdx.x;
    const int lane = t & 31;
    const int w = t >> 5;

    const int rel = rel_ids[b * NT + t];
    const int id  = input_ids[b * NT + t];
    const int inc = (rel > 0) ? 1 : 0;

    // ---- inclusive warp cumsum of inc ----
    int x = inc;
#pragma unroll
    for (int off = 1; off < 32; off <<= 1) {
        int v = __shfl_up_sync(0xFFFFFFFFu, x, off);
        if (lane >= off) x += v;
    }
    if (lane == 31) wred[w] = x;
    __syncthreads();
    if (w == 0) {
        int y = (lane < 16) ? wred[lane] : 0;
#pragma unroll
        for (int off = 1; off < 16; off <<= 1) {
            int v = __shfl_up_sync(0xFFFFFFFFu, y, off);
            if (lane >= off) y += v;
        }
        if (lane < 16) wred[lane] = y;
    }
    __syncthreads();
    const int c = x - inc + ((w > 0) ? wred[w - 1] : 0);  // exclusive cumsum

    const int prev_rel = (t > 0) ? rel_ids[b * NT + t - 1] : 0;
    const int reset = (rel == 0 && prev_rel > 0);
    __syncthreads();  // wred reuse

    // ---- inclusive warp cummax of (reset ? c : 0) ----
    int m = reset ? c : 0;
#pragma unroll
    for (int off = 1; off < 32; off <<= 1) {
        int v = __shfl_up_sync(0xFFFFFFFFu, m, off);
        if (lane >= off) m = max(m, v);
    }
    if (lane == 31) wred[w] = m;
    __syncthreads();
    if (w == 0) {
        int y = (lane < 16) ? wred[lane] : 0;
#pragma unroll
        for (int off = 1; off < 16; off <<= 1) {
            int v = __shfl_up_sync(0xFFFFFFFFu, y, off);
            if (lane >= off) y = max(y, v);
        }
        if (lane < 16) wred[lane] = y;
    }
    __syncthreads();
    const int baseline = max(m, (w > 0) ? wred[w - 1] : 0);
    const int cp = c - baseline;

    const int role = (id <= 4) ? 3 : ((rel == 0) ? 2 : 0);
    g_packed[b * NT + t] = cp | (role << 16);
}

// streaming (evict-first) float4 store
__device__ __forceinline__ void stcs4(float4* p, float4 v) {
    asm volatile("st.global.cs.v4.f32 [%0], {%1,%2,%3,%4};"
                 :: "l"(p), "f"(v.x), "f"(v.y), "f"(v.z), "f"(v.w) : "memory");
}

// ---------------------------------------------------------------------------
// Kernel B: embedding sum. Grid (NT, NB/BPB) = (512, 8), 256 thr/block,
// one float4 column per thread. The three reachable (base + 0.2*role) rows
// are precombined in 12 registers; inner loop over BPB batches reads only
// the chain float4 and streams the output. launch_bounds forces 6 CTA/SM.
// ---------------------------------------------------------------------------
__global__ __launch_bounds__(256, 6) void gpe_emb_kernel(
    const float* __restrict__ seq_table,
    const float* __restrict__ chain_table,
    const float* __restrict__ depth_table,
    const float* __restrict__ role_table,
    float* __restrict__ out) {

    const int t = blockIdx.x;
    const int b0 = blockIdx.y * BPB;
    const int tid = threadIdx.x;
    const int d = tid * 4;

    __shared__ int spk[BPB];
    if (tid < BPB) spk[tid] = g_packed[(b0 + tid) * NT + t];

    const float4 s4 = *(const float4*)(seq_table + (size_t)t * ND + d);
    const float4 dp = *(const float4*)(depth_table + d);  // depth row 0 always
    float bx = s4.x + 0.3f * dp.x;
    float by = s4.y + 0.3f * dp.y;
    float bz = s4.z + 0.3f * dp.z;
    float bw = s4.w + 0.3f * dp.w;

    const float4 q0 = *(const float4*)(role_table + 0 * ND + d);
    const float4 q2 = *(const float4*)(role_table + 2 * ND + d);
    const float4 q3 = *(const float4*)(role_table + 3 * ND + d);
    // precombined base + 0.2*role for the three reachable roles
    float4 m0, m2, m3;
    m0.x = bx + 0.2f * q0.x; m0.y = by + 0.2f * q0.y; m0.z = bz + 0.2f * q0.z; m0.w = bw + 0.2f * q0.w;
    m2.x = bx + 0.2f * q2.x; m2.y = by + 0.2f * q2.y; m2.z = bz + 0.2f * q2.z; m2.w = bw + 0.2f * q2.w;
    m3.x = bx + 0.2f * q3.x; m3.y = by + 0.2f * q3.y; m3.z = bz + 0.2f * q3.z; m3.w = bw + 0.2f * q3.w;

    __syncthreads();

#pragma unroll 4
    for (int i = 0; i < BPB; i++) {
        const int pk = spk[i];
        const int cp = pk & 0xFFFF;
        const int role = pk >> 16;

        const float4 c4 = *(const float4*)(chain_table + (size_t)cp * ND + d);
        const float4 m4 = (role == 3) ? m3 : ((role == 2) ? m2 : m0);

        float4 o;
        o.x = m4.x + 0.5f * c4.x;
        o.y = m4.y + 0.5f * c4.y;
        o.z = m4.z + 0.5f * c4.z;
        o.w = m4.w + 0.5f * c4.w;

        stcs4((float4*)(out + ((size_t)(b0 + i) * NT + t) * ND + d), o);
    }
}

extern "C" void kernel_launch(void* const* d_in, const int* in_sizes, int n_in,
                              void* d_out, int out_size) {
    const int* input_ids   = (const int*)d_in[0];
    const int* rel_ids     = (const int*)d_in[1];
    const float* seq_table = (const float*)d_in[2];
    const float* chain_tab = (const float*)d_in[3];
    const float* depth_tab = (const float*)d_in[4];
    const float* role_tab  = (const float*)d_in[5];
    float* out = (float*)d_out;

    gpe_scan_kernel<<<NB, NT>>>(input_ids, rel_ids);
    dim3 grid(NT, NB / BPB);
    gpe_emb_kernel<<<grid, 256>>>(seq_table, chain_tab, depth_tab, role_tab, out);
}

// round 4
// speedup vs baseline: 1.0012x; 1.0012x over previous
#include <cuda_runtime.h>
#include <cuda_bf16.h>

#define NB 64
#define NT 512
#define ND 1024
#define BPB 16  // batches per block in kernel B

// scratch: packed (chain_pos | role_idx<<16) per (b,t). Static device global.
__device__ int g_packed[NB * NT];

// ---------------------------------------------------------------------------
// Kernel A: per-batch-row prefix scans (cumsum + cummax) via warp shuffles.
// role remapped to dense idx: 0->0, 2->1, 3->2.
// ---------------------------------------------------------------------------
__global__ __launch_bounds__(512) void gpe_scan_kernel(
    const int* __restrict__ input_ids,
    const int* __restrict__ rel_ids) {
    __shared__ int wred[16];

    const int b = blockIdx.x;
    const int t = threadIdx.x;
    const int lane = t & 31;
    const int w = t >> 5;

    const int rel = rel_ids[b * NT + t];
    const int id  = input_ids[b * NT + t];
    const int inc = (rel > 0) ? 1 : 0;

    // ---- inclusive warp cumsum of inc ----
    int x = inc;
#pragma unroll
    for (int off = 1; off < 32; off <<= 1) {
        int v = __shfl_up_sync(0xFFFFFFFFu, x, off);
        if (lane >= off) x += v;
    }
    if (lane == 31) wred[w] = x;
    __syncthreads();
    if (w == 0) {
        int y = (lane < 16) ? wred[lane] : 0;
#pragma unroll
        for (int off = 1; off < 16; off <<= 1) {
            int v = __shfl_up_sync(0xFFFFFFFFu, y, off);
            if (lane >= off) y += v;
        }
        if (lane < 16) wred[lane] = y;
    }
    __syncthreads();
    const int c = x - inc + ((w > 0) ? wred[w - 1] : 0);  // exclusive cumsum

    const int prev_rel = (t > 0) ? rel_ids[b * NT + t - 1] : 0;
    const int reset = (rel == 0 && prev_rel > 0);
    __syncthreads();  // wred reuse

    // ---- inclusive warp cummax of (reset ? c : 0) ----
    int m = reset ? c : 0;
#pragma unroll
    for (int off = 1; off < 32; off <<= 1) {
        int v = __shfl_up_sync(0xFFFFFFFFu, m, off);
        if (lane >= off) m = max(m, v);
    }
    if (lane == 31) wred[w] = m;
    __syncthreads();
    if (w == 0) {
        int y = (lane < 16) ? wred[lane] : 0;
#pragma unroll
        for (int off = 1; off < 16; off <<= 1) {
            int v = __shfl_up_sync(0xFFFFFFFFu, y, off);
            if (lane >= off) y = max(y, v);
        }
        if (lane < 16) wred[lane] = y;
    }
    __syncthreads();
    const int baseline = max(m, (w > 0) ? wred[w - 1] : 0);
    const int cp = c - baseline;

    // dense role idx: 2 for input_ids<=4 (role 3), 1 if rel==0 (role 2), else 0 (role 0)
    const int ridx = (id <= 4) ? 2 : ((rel == 0) ? 1 : 0);
    g_packed[b * NT + t] = cp | (ridx << 16);
}

// streaming (evict-first) float4 store
__device__ __forceinline__ void stcs4(float4* p, float4 v) {
    asm volatile("st.global.cs.v4.f32 [%0], {%1,%2,%3,%4};"
                 :: "l"(p), "f"(v.x), "f"(v.y), "f"(v.z), "f"(v.w) : "memory");
}

// ---------------------------------------------------------------------------
// Kernel B: embedding sum. Grid (NT, NB/BPB) = (512, 4), 256 thr/block.
// Preamble stages the three precombined rows (seq + 0.3*depth + 0.2*role_r)
// into shared memory. Inner loop per batch: 1 LDS.128 (block-uniform row,
// conflict-free) + 1 LDG.128 chain gather + 4 FFMA + 1 streaming STG.128.
// ---------------------------------------------------------------------------
__global__ __launch_bounds__(256) void gpe_emb_kernel(
    const float* __restrict__ seq_table,
    const float* __restrict__ chain_table,
    const float* __restrict__ depth_table,
    const float* __restrict__ role_table,
    float* __restrict__ out) {

    __shared__ float4 sm[3 * 256];  // 12 KB: three combined rows
    __shared__ int spk[BPB];

    const int t = blockIdx.x;
    const int b0 = blockIdx.y * BPB;
    const int tid = threadIdx.x;
    const int d = tid * 4;

    if (tid < BPB) spk[tid] = g_packed[(b0 + tid) * NT + t];

    {
        const float4 s4 = *(const float4*)(seq_table + (size_t)t * ND + d);
        const float4 dp = *(const float4*)(depth_table + d);  // depth row 0 always
        const float bx = s4.x + 0.3f * dp.x;
        const float by = s4.y + 0.3f * dp.y;
        const float bz = s4.z + 0.3f * dp.z;
        const float bw = s4.w + 0.3f * dp.w;

        const float4 q0 = *(const float4*)(role_table + 0 * ND + d);
        const float4 q2 = *(const float4*)(role_table + 2 * ND + d);
        const float4 q3 = *(const float4*)(role_table + 3 * ND + d);

        float4 v;
        v.x = bx + 0.2f * q0.x; v.y = by + 0.2f * q0.y; v.z = bz + 0.2f * q0.z; v.w = bw + 0.2f * q0.w;
        sm[0 * 256 + tid] = v;
        v.x = bx + 0.2f * q2.x; v.y = by + 0.2f * q2.y; v.z = bz + 0.2f * q2.z; v.w = bw + 0.2f * q2.w;
        sm[1 * 256 + tid] = v;
        v.x = bx + 0.2f * q3.x; v.y = by + 0.2f * q3.y; v.z = bz + 0.2f * q3.z; v.w = bw + 0.2f * q3.w;
        sm[2 * 256 + tid] = v;
    }
    __syncthreads();

    float* outp = out + ((size_t)b0 * NT + t) * ND + d;

#pragma unroll 4
    for (int i = 0; i < BPB; i++) {
        const int pk = spk[i];
        const int cp = pk & 0xFFFF;
        const int ridx = pk >> 16;

        const float4 c4 = *(const float4*)(chain_table + (size_t)cp * ND + d);
        const float4 m4 = sm[ridx * 256 + tid];

        float4 o;
        o.x = m4.x + 0.5f * c4.x;
        o.y = m4.y + 0.5f * c4.y;
        o.z = m4.z + 0.5f * c4.z;
        o.w = m4.w + 0.5f * c4.w;

        stcs4((float4*)outp, o);
        outp += (size_t)NT * ND;
    }
}

extern "C" void kernel_launch(void* const* d_in, const int* in_sizes, int n_in,
                              void* d_out, int out_size) {
    const int* input_ids   = (const int*)d_in[0];
    const int* rel_ids     = (const int*)d_in[1];
    const float* seq_table = (const float*)d_in[2];
    const float* chain_tab = (const float*)d_in[3];
    const float* depth_tab = (const float*)d_in[4];
    const float* role_tab  = (const float*)d_in[5];
    float* out = (float*)d_out;

    gpe_scan_kernel<<<NB, NT>>>(input_ids, rel_ids);
    dim3 grid(NT, NB / BPB);
    gpe_emb_kernel<<<grid, 256>>>(seq_table, chain_tab, depth_tab, role_tab, out);
}